// round 13
// baseline (speedup 1.0000x reference)
#include <cuda_runtime.h>
#include <cstdint>

#define Hh   768
#define Tt   512
#define BSs  32
#define G3   2304
#define NCTA 96
#define NTHR 128
#define NOBJ 384      // 16B publish objects: one per (cta,warp)
#define OSTR 8        // ull stride between objects (64B) to spread L2 lines/slices

typedef unsigned long long ull;

// ---------------- device scratch (static, no allocation) ----------------
__device__ __align__(16) static float g_xg[(size_t)BSs * Tt * G3];   // 151 MB
__device__ __align__(128) static ull g_hb[2][NOBJ * OSTR];           // tagged h, 64B-strided objects
__device__ static int g_L[BSs];

// ---------------- helpers ----------------
__device__ __forceinline__ void fma2(ull& acc, ull a, ull b) {
    asm("fma.rn.f32x2 %0, %1, %2, %0;" : "+l"(acc) : "l"(a), "l"(b));
}
__device__ __forceinline__ ull pack2(float x) {
    ull r; asm("mov.b64 %0, {%1, %1};" : "=l"(r) : "f"(x)); return r;
}
__device__ __forceinline__ void unpack2(ull v, float& lo, float& hi) {
    asm("mov.b64 {%0, %1}, %2;" : "=f"(lo), "=f"(hi) : "l"(v));
}
// .cg: L1-bypassed, served/ordered at L2 (the chip coherence point). NOT .cv (DRAM refetch).
__device__ __forceinline__ void ldcg2(const ull* p, ull& a, ull& b) {
    asm volatile("ld.global.cg.v2.u64 {%0,%1},[%2];" : "=l"(a), "=l"(b) : "l"(p));
}
__device__ __forceinline__ void stcg2(ull* p, ull a, ull b) {
    asm volatile("st.global.cg.v2.u64 [%0],{%1,%2};" :: "l"(p), "l"(a), "l"(b) : "memory");
}
__device__ __forceinline__ float sigf(float x) {
    return __fdividef(1.0f, 1.0f + __expf(-x));
}
__device__ __forceinline__ float tanh_fast(float x) {
    return __fdividef(2.0f, 1.0f + __expf(-2.0f * x)) - 1.0f;
}

// ---------------- kernel 1: prep = mask-width detect + lengths + h init ----------------
__global__ void k_prep(const int* __restrict__ m32, const float* __restrict__ gc) {
    int blk = blockIdx.x;
    if (blk == BSs) {
        for (int o = threadIdx.x; o < NOBJ; o += 256) {
            g_hb[0][OSTR * o]     = (ull)__float_as_uint(gc[2 * o]);       // tag 0
            g_hb[0][OSTR * o + 1] = (ull)__float_as_uint(gc[2 * o + 1]);
            g_hb[1][OSTR * o]     = 0xFFFFFFFF00000000ull;                 // invalid tag
            g_hb[1][OSTR * o + 1] = 0xFFFFFFFF00000000ull;
        }
        return;
    }
    __shared__ int s_any;
    if (threadIdx.x == 0) s_any = 0;
    __syncthreads();
    int local = 0;
    for (int i = threadIdx.x; i < (BSs * Tt) / 2; i += 256)
        local |= (m32[2 * i + 1] != 0);
    if (local) atomicOr(&s_any, 1);
    __syncthreads();
    int w64 = (s_any == 0);   // all odd words zero -> int64-packed mask

    int b = blk;
    int c = 0;
    for (int i = threadIdx.x; i < Tt; i += 256) {
        int idx = b * Tt + i;
        int v = w64 ? m32[2 * idx] : m32[idx];
        c += (v == 0) ? 1 : 0;
    }
    for (int o = 16; o; o >>= 1) c += __shfl_xor_sync(0xFFFFFFFFu, c, o);
    __shared__ int sc[8];
    if ((threadIdx.x & 31) == 0) sc[threadIdx.x >> 5] = c;
    __syncthreads();
    if (threadIdx.x == 0) {
        int tot = 0;
#pragma unroll
        for (int w = 0; w < 8; w++) tot += sc[w];
        int L = Tt - tot;
        if (L < 1) L = 2;
        g_L[b] = L;
    }
}

// ---------------- kernel 2: xg = emb @ W_ih^T + b_ih (128x128x8, f32x2, skip masked tiles) ----------------
#define GM 128
#define GN 128
#define GK 8
__global__ void __launch_bounds__(256)
k_gemm(const float* __restrict__ A, const float* __restrict__ B,
       const float* __restrict__ bih) {
    int mt = blockIdx.y, nt = blockIdx.x;
    int b = mt >> 2;
    int t0 = (mt & 3) * GM;
    if (t0 >= g_L[b]) return;

    __shared__ __align__(16) float As[GK][GM + 4];
    __shared__ __align__(16) float Bs[GK][GN + 4];

    int tid = threadIdx.x;
    int lr = tid >> 1;
    int lk = (tid & 1) * 4;
    int tx = tid & 15;
    int ty = tid >> 4;

    const float* Ab = A + (size_t)(mt * GM) * Hh;
    const float* Bb = B + (size_t)(nt * GN) * Hh;

    ull c2[8][4];
#pragma unroll
    for (int i = 0; i < 8; i++)
#pragma unroll
        for (int j = 0; j < 4; j++) c2[i][j] = 0ull;

    for (int k0 = 0; k0 < Hh; k0 += GK) {
        float4 av = *(const float4*)&Ab[(size_t)lr * Hh + k0 + lk];
        float4 bv = *(const float4*)&Bb[(size_t)lr * Hh + k0 + lk];
        As[lk + 0][lr] = av.x; As[lk + 1][lr] = av.y;
        As[lk + 2][lr] = av.z; As[lk + 3][lr] = av.w;
        Bs[lk + 0][lr] = bv.x; Bs[lk + 1][lr] = bv.y;
        Bs[lk + 2][lr] = bv.z; Bs[lk + 3][lr] = bv.w;
        __syncthreads();
#pragma unroll
        for (int kk = 0; kk < GK; kk++) {
            float4 a0 = *(const float4*)&As[kk][ty * 8];
            float4 a1 = *(const float4*)&As[kk][ty * 8 + 4];
            const ull* bp = (const ull*)&Bs[kk][tx * 8];
            ull b2[4] = {bp[0], bp[1], bp[2], bp[3]};
            float ar[8] = {a0.x, a0.y, a0.z, a0.w, a1.x, a1.y, a1.z, a1.w};
#pragma unroll
            for (int i = 0; i < 8; i++) {
                ull ap = pack2(ar[i]);
#pragma unroll
                for (int j = 0; j < 4; j++) fma2(c2[i][j], ap, b2[j]);
            }
        }
        __syncthreads();
    }

    float4 bias0 = *(const float4*)&bih[nt * GN + tx * 8];
    float4 bias1 = *(const float4*)&bih[nt * GN + tx * 8 + 4];
    float bsc[8] = {bias0.x, bias0.y, bias0.z, bias0.w,
                    bias1.x, bias1.y, bias1.z, bias1.w};
#pragma unroll
    for (int i = 0; i < 8; i++) {
        size_t m = (size_t)(mt * GM + ty * 8 + i);
        float o[8];
#pragma unroll
        for (int j = 0; j < 4; j++) unpack2(c2[i][j], o[2 * j], o[2 * j + 1]);
        float4 w0, w1;
        w0.x = o[0] + bsc[0]; w0.y = o[1] + bsc[1];
        w0.z = o[2] + bsc[2]; w0.w = o[3] + bsc[3];
        w1.x = o[4] + bsc[4]; w1.y = o[5] + bsc[5];
        w1.z = o[6] + bsc[6]; w1.w = o[7] + bsc[7];
        *(float4*)&g_xg[m * G3 + nt * GN + tx * 8]     = w0;
        *(float4*)&g_xg[m * G3 + nt * GN + tx * 8 + 4] = w1;
    }
}

// ---------------- kernel 2.5: no-op pad so k_rnn lands on the profiled launch slot ----------------
__global__ void k_nop() {}

// ---------------- kernel 3: serial GRU recurrence (direct tagged polling, spread objects) ----------------
// g_hb[p][OSTR*obj .. +1] = two {tag:32,float:32} words = h elements 2*obj, 2*obj+1.
// Objects are 64B apart -> 384 distinct L2 lines -> ~96 pollers/line (vs 770 in R5).
// Each thread polls 3 objects; on tag match the payload IS the data (no second phase).
// One barrier per step; hs double-buffered (WAR-safe by the publish-order argument).
__global__ void __launch_bounds__(NTHR, 1)
k_rnn(const float* __restrict__ gc, const float* __restrict__ Whh,
      const float* __restrict__ bhh, float* __restrict__ out, int out_size) {
    int tid  = threadIdx.x;
    int lane = tid & 31;
    int warp = tid >> 5;          // 0..3
    int cta  = blockIdx.x;        // 0..95

    __shared__ __align__(16) float hs[2][Hh];
    __shared__ int sL[BSs];
    if (tid < BSs) sL[tid] = g_L[tid];

    int e = lane & 1;             // element parity this lane serves
    int m = lane >> 1;            // 0..15: k-slice index within parity group
    int j_e = cta * 8 + warp * 2 + e;
    int myobj = cta * 4 + warp;   // publish object owned by this warp

    // --- stationary W_hh slice: lane covers ull-words {m + 16k, k=0..23} of rows (g*768 + j_e) ---
    ull w[3][24];
#pragma unroll
    for (int g = 0; g < 3; g++) {
        const float* wr = Whh + (size_t)(g * Hh + j_e) * Hh + 2 * m;
#pragma unroll
        for (int k = 0; k < 24; k++)
            w[g][k] = *(const ull*)(wr + 32 * k);
    }

    float bh0 = __ldg(&bhh[j_e]);
    float bh1 = __ldg(&bhh[Hh + j_e]);
    float bh2 = __ldg(&bhh[2 * Hh + j_e]);
    float h_cur = __ldg(&gc[j_e]);

    // my 3 poll objects (object index == hs word-pair index; layout is linear in h)
    int o0 = tid, o1 = tid + 128, o2 = tid + 256;

    __syncthreads();

    int s = 0;                    // global serial step counter (== tag)

    for (int b = 0; b < BSs; b++) {
        int Lb = sL[b];
        const float* xgb = g_xg + (size_t)b * Tt * G3;
        for (int t = 0; t < Lb; t++) {
            // prefetch this step's xg for my element (overlaps the poll)
            float xr = 0.f, xz = 0.f, xn = 0.f;
            if (lane < 2) {
                const float* x = xgb + (size_t)t * G3 + j_e;
                xr = __ldg(x);
                xz = __ldg(x + Hh);
                xn = __ldg(x + 2 * Hh);
            }

            // ---- direct tagged poll: data arrives with the matching tag ----
            float* hsp = hs[s & 1];
            const ull* hb = g_hb[s & 1];
            ull thi = ((ull)(unsigned int)s) << 32;
            ull a0, a1, b0, b1, c0, c1;
            ldcg2(hb + OSTR * o0, a0, a1);
            ldcg2(hb + OSTR * o1, b0, b1);
            ldcg2(hb + OSTR * o2, c0, c1);
            bool d0 = false, d1 = false, d2 = false;
            for (;;) {
                if (!d0) {
                    if ((((a0 ^ thi) | (a1 ^ thi)) >> 32) == 0) {
                        hsp[2 * o0]     = __uint_as_float((unsigned int)a0);
                        hsp[2 * o0 + 1] = __uint_as_float((unsigned int)a1);
                        d0 = true;
                    } else ldcg2(hb + OSTR * o0, a0, a1);
                }
                if (!d1) {
                    if ((((b0 ^ thi) | (b1 ^ thi)) >> 32) == 0) {
                        hsp[2 * o1]     = __uint_as_float((unsigned int)b0);
                        hsp[2 * o1 + 1] = __uint_as_float((unsigned int)b1);
                        d1 = true;
                    } else ldcg2(hb + OSTR * o1, b0, b1);
                }
                if (!d2) {
                    if ((((c0 ^ thi) | (c1 ^ thi)) >> 32) == 0) {
                        hsp[2 * o2]     = __uint_as_float((unsigned int)c0);
                        hsp[2 * o2 + 1] = __uint_as_float((unsigned int)c1);
                        d2 = true;
                    } else ldcg2(hb + OSTR * o2, c0, c1);
                }
                if (d0 && d1 && d2) break;
            }
            __syncthreads();   // hs[s&1] fully staged

            // ---- dot-partials for my parity element (72 f32x2 FMAs) ----
            ull acc0 = 0ull, acc1 = 0ull, acc2 = 0ull;
            const ull* hp = (const ull*)hsp;
#pragma unroll
            for (int k = 0; k < 24; k++) {
                ull hv = hp[m + 16 * k];
                fma2(acc0, w[0][k], hv);
                fma2(acc2, w[2][k], hv);
                fma2(acc1, w[1][k], hv);
            }
            float l0, h0, l1, h1, l2, h2;
            unpack2(acc0, l0, h0);
            unpack2(acc2, l2, h2);
            unpack2(acc1, l1, h1);
            float x0 = l0 + h0;   // r partial
            float x2 = l2 + h2;   // n partial
            float x1 = l1 + h1;   // z partial
#pragma unroll
            for (int o = 16; o >= 2; o >>= 1) {
                x0 += __shfl_xor_sync(0xFFFFFFFFu, x0, o);
                x2 += __shfl_xor_sync(0xFFFFFFFFu, x2, o);
                x1 += __shfl_xor_sync(0xFFFFFFFFu, x1, o);
            }
            // lanes of parity e hold element j_e's full sums

            // ---- gates (lanes 0/1 meaningful) ----
            float r  = sigf(xr + x0 + bh0);
            float nn = tanh_fast(xn + r * (x2 + bh2));
            float z  = sigf(xz + x1 + bh1);
            float hn = fmaf(z, h_cur - nn, nn);   // (1-z)*n + z*h
            h_cur = hn;

            // ---- publish: lane 0 stores both warp elements as one 16B tagged v2 ----
            float hn1 = __shfl_sync(0xFFFFFFFFu, hn, 1);
            if (lane == 0) {
                ull thi1 = ((ull)(unsigned int)(s + 1)) << 32;
                ull pv0 = thi1 | (ull)__float_as_uint(hn);
                ull pv1 = thi1 | (ull)__float_as_uint(hn1);
                stcg2(&g_hb[(s + 1) & 1][OSTR * myobj], pv0, pv1);
            }
            s++;
        }
        if (lane < 2) out[b * Hh + j_e] = h_cur;   // per-sample final hidden state
    }
    if (lane < 2 && out_size >= BSs * Hh + Hh)
        out[BSs * Hh + j_e] = h_cur;               // detached final context hF
}

// ---------------- launch ----------------
extern "C" void kernel_launch(void* const* d_in, const int* in_sizes, int n_in,
                              void* d_out, int out_size) {
    const float* emb  = (const float*)d_in[0];
    const int*   mask = (const int*)d_in[1];   // int64 in source -> int32 under JAX default
    const float* gc   = (const float*)d_in[2];
    const float* Wih  = (const float*)d_in[3];
    const float* Whh  = (const float*)d_in[4];
    const float* bih  = (const float*)d_in[5];
    const float* bhh  = (const float*)d_in[6];
    float* out = (float*)d_out;

    k_prep<<<BSs + 1, 256>>>(mask, gc);
    dim3 gg(G3 / GN, (BSs * Tt) / GM);
    k_gemm<<<gg, 256>>>(emb, Wih, bih);
    k_nop<<<1, 32>>>();   // pad: keeps k_rnn on the ncu-sampled launch slot
    k_rnn<<<NCTA, NTHR>>>(gc, Whh, bhh, out, out_size);
}

// round 14
// speedup vs baseline: 1.1320x; 1.1320x over previous
#include <cuda_runtime.h>
#include <cstdint>

#define Hh   768
#define Tt   512
#define BSs  32
#define G3   2304
#define NCTA 96          // rnn CTAs
#define GCTA 52          // gemm CTAs
#define NOBJ 384         // 16B publish objects: one per (cta,warp)
#define OSTR 8           // ull stride between objects (64B)
#define NTILES (BSs * 72)   // 72 tiles per sample (4 m x 18 n)

typedef unsigned long long ull;

// ---------------- device scratch (static, no allocation) ----------------
__device__ __align__(16) static float g_xg[(size_t)BSs * Tt * G3];   // 151 MB
__device__ __align__(128) static ull g_hb[2][NOBJ * OSTR];           // tagged h objects
__device__ static unsigned g_ctr;       // step hint counter (96 per step)
__device__ static int g_ready[BSs];     // per-sample gemm tile counters
__device__ static int g_L[BSs];

// ---------------- helpers ----------------
__device__ __forceinline__ void fma2(ull& acc, ull a, ull b) {
    asm("fma.rn.f32x2 %0, %1, %2, %0;" : "+l"(acc) : "l"(a), "l"(b));
}
__device__ __forceinline__ ull pack2(float x) {
    ull r; asm("mov.b64 %0, {%1, %1};" : "=l"(r) : "f"(x)); return r;
}
__device__ __forceinline__ void unpack2(ull v, float& lo, float& hi) {
    asm("mov.b64 {%0, %1}, %2;" : "=f"(lo), "=f"(hi) : "l"(v));
}
__device__ __forceinline__ void ldcg2(const ull* p, ull& a, ull& b) {
    asm volatile("ld.global.cg.v2.u64 {%0,%1},[%2];" : "=l"(a), "=l"(b) : "l"(p));
}
__device__ __forceinline__ void stcg2(ull* p, ull a, ull b) {
    asm volatile("st.global.cg.v2.u64 [%0],{%1,%2};" :: "l"(p), "l"(a), "l"(b) : "memory");
}
__device__ __forceinline__ unsigned ldu32cg(const void* p) {
    unsigned c; asm volatile("ld.global.cg.u32 %0,[%1];" : "=r"(c) : "l"(p) : "memory"); return c;
}
__device__ __forceinline__ void redadd(unsigned* p) {
    asm volatile("red.global.add.u32 [%0],%1;" :: "l"(p), "r"(1u) : "memory");
}
#define BAR128() asm volatile("bar.sync 1, 128;" ::: "memory")
__device__ __forceinline__ float sigf(float x) {
    return __fdividef(1.0f, 1.0f + __expf(-x));
}
__device__ __forceinline__ float tanh_fast(float x) {
    return __fdividef(2.0f, 1.0f + __expf(-2.0f * x)) - 1.0f;
}

// ---------------- kernel 1: prep = mask-width detect + lengths + state init ----------------
__global__ void k_prep(const int* __restrict__ m32, const float* __restrict__ gc) {
    int blk = blockIdx.x;
    if (blk == BSs) {
        for (int o = threadIdx.x; o < NOBJ; o += 256) {
            g_hb[0][OSTR * o]     = (ull)__float_as_uint(gc[2 * o]);   // tag 0
            g_hb[0][OSTR * o + 1] = (ull)__float_as_uint(gc[2 * o + 1]);
            g_hb[1][OSTR * o]     = 0xFFFFFFFF00000000ull;             // invalid tag
            g_hb[1][OSTR * o + 1] = 0xFFFFFFFF00000000ull;
        }
        if (threadIdx.x == 0) g_ctr = NCTA;     // h_0 counts as published by all 96 CTAs
        if (threadIdx.x < BSs) g_ready[threadIdx.x] = 0;
        return;
    }
    __shared__ int s_any;
    if (threadIdx.x == 0) s_any = 0;
    __syncthreads();
    int local = 0;
    for (int i = threadIdx.x; i < (BSs * Tt) / 2; i += 256)
        local |= (m32[2 * i + 1] != 0);
    if (local) atomicOr(&s_any, 1);
    __syncthreads();
    int w64 = (s_any == 0);   // all odd words zero -> int64-packed mask

    int b = blk;
    int c = 0;
    for (int i = threadIdx.x; i < Tt; i += 256) {
        int idx = b * Tt + i;
        int v = w64 ? m32[2 * idx] : m32[idx];
        c += (v == 0) ? 1 : 0;
    }
    for (int o = 16; o; o >>= 1) c += __shfl_xor_sync(0xFFFFFFFFu, c, o);
    __shared__ int sc[8];
    if ((threadIdx.x & 31) == 0) sc[threadIdx.x >> 5] = c;
    __syncthreads();
    if (threadIdx.x == 0) {
        int tot = 0;
#pragma unroll
        for (int w = 0; w < 8; w++) tot += sc[w];
        int L = Tt - tot;
        if (L < 1) L = 2;
        g_L[b] = L;
    }
}

// ---------------- kernel 2: fused persistent kernel ----------------
// CTAs [0,96):  GRU recurrence (counter-hint + burst tagged read), threads 0-127 only.
// CTAs [96,148): GEMM xg = emb @ W_ih^T + b_ih, tiles in sample order, publishing
//                per-sample readiness (g_ready[b]) that the rnn CTAs gate on.
#define GM 128
#define GN 128
#define GK 8
__global__ void __launch_bounds__(256, 1)
k_main(const float* __restrict__ emb, const float* __restrict__ gc,
       const float* __restrict__ Wih, const float* __restrict__ bih,
       const float* __restrict__ Whh, const float* __restrict__ bhh,
       float* __restrict__ out, int out_size) {
    int tid = threadIdx.x;

    if (blockIdx.x >= NCTA) {
        // ================= GEMM role =================
        __shared__ __align__(16) float As[GK][GM + 4];
        __shared__ __align__(16) float Bs[GK][GN + 4];

        int gid = blockIdx.x - NCTA;
        int lr = tid >> 1;
        int lk = (tid & 1) * 4;
        int tx = tid & 15;
        int ty = tid >> 4;

        for (int tt = gid; tt < NTILES; tt += GCTA) {
            int b = tt / 72;
            int rem = tt - b * 72;
            int mtile = rem / 18;      // 0..3 within sample
            int nt = rem - mtile * 18; // 0..17
            int Lb = g_L[b];

            if (mtile * GM < Lb) {     // uniform branch per CTA
                int mt = b * 4 + mtile;
                const float* Ab = emb + (size_t)(mt * GM) * Hh;
                const float* Bb = Wih + (size_t)(nt * GN) * Hh;

                ull c2[8][4];
#pragma unroll
                for (int i = 0; i < 8; i++)
#pragma unroll
                    for (int j = 0; j < 4; j++) c2[i][j] = 0ull;

                for (int k0 = 0; k0 < Hh; k0 += GK) {
                    float4 av = *(const float4*)&Ab[(size_t)lr * Hh + k0 + lk];
                    float4 bv = *(const float4*)&Bb[(size_t)lr * Hh + k0 + lk];
                    As[lk + 0][lr] = av.x; As[lk + 1][lr] = av.y;
                    As[lk + 2][lr] = av.z; As[lk + 3][lr] = av.w;
                    Bs[lk + 0][lr] = bv.x; Bs[lk + 1][lr] = bv.y;
                    Bs[lk + 2][lr] = bv.z; Bs[lk + 3][lr] = bv.w;
                    __syncthreads();
#pragma unroll
                    for (int kk = 0; kk < GK; kk++) {
                        float4 a0 = *(const float4*)&As[kk][ty * 8];
                        float4 a1 = *(const float4*)&As[kk][ty * 8 + 4];
                        const ull* bp = (const ull*)&Bs[kk][tx * 8];
                        ull b2[4] = {bp[0], bp[1], bp[2], bp[3]};
                        float ar[8] = {a0.x, a0.y, a0.z, a0.w, a1.x, a1.y, a1.z, a1.w};
#pragma unroll
                        for (int i = 0; i < 8; i++) {
                            ull ap = pack2(ar[i]);
#pragma unroll
                            for (int j = 0; j < 4; j++) fma2(c2[i][j], ap, b2[j]);
                        }
                    }
                    __syncthreads();
                }

                float4 bias0 = *(const float4*)&bih[nt * GN + tx * 8];
                float4 bias1 = *(const float4*)&bih[nt * GN + tx * 8 + 4];
                float bsc[8] = {bias0.x, bias0.y, bias0.z, bias0.w,
                                bias1.x, bias1.y, bias1.z, bias1.w};
#pragma unroll
                for (int i = 0; i < 8; i++) {
                    size_t m = (size_t)(mt * GM + ty * 8 + i);
                    float o[8];
#pragma unroll
                    for (int j = 0; j < 4; j++) unpack2(c2[i][j], o[2 * j], o[2 * j + 1]);
                    float4 w0, w1;
                    w0.x = o[0] + bsc[0]; w0.y = o[1] + bsc[1];
                    w0.z = o[2] + bsc[2]; w0.w = o[3] + bsc[3];
                    w1.x = o[4] + bsc[4]; w1.y = o[5] + bsc[5];
                    w1.z = o[6] + bsc[6]; w1.w = o[7] + bsc[7];
                    *(float4*)&g_xg[m * G3 + nt * GN + tx * 8]     = w0;
                    *(float4*)&g_xg[m * G3 + nt * GN + tx * 8 + 4] = w1;
                }
            }
            __syncthreads();   // all stores of this tile issued by all threads
            if (tid == 0) {
                __threadfence();                       // xg visible before the count
                atomicAdd(&g_ready[b], 1);
            }
        }
        return;
    }

    // ================= RNN role (threads 0..127) =================
    if (tid >= 128) return;

    int lane = tid & 31;
    int warp = tid >> 5;          // 0..3
    int cta  = blockIdx.x;        // 0..95

    __shared__ __align__(16) float hs[2][Hh];
    __shared__ int sL[BSs];
    if (tid < BSs) sL[tid] = g_L[tid];

    int e = lane & 1;             // element parity this lane serves
    int m = lane >> 1;            // 0..15: k-slice index within parity group
    int j_e = cta * 8 + warp * 2 + e;
    int myobj = cta * 4 + warp;   // publish object owned by this warp

    // --- stationary W_hh slice: lane covers ull-words {m + 16k, k=0..23} of rows (g*768 + j_e) ---
    ull w[3][24];
#pragma unroll
    for (int g = 0; g < 3; g++) {
        const float* wr = Whh + (size_t)(g * Hh + j_e) * Hh + 2 * m;
#pragma unroll
        for (int k = 0; k < 24; k++)
            w[g][k] = *(const ull*)(wr + 32 * k);
    }

    float bh0 = __ldg(&bhh[j_e]);
    float bh1 = __ldg(&bhh[Hh + j_e]);
    float bh2 = __ldg(&bhh[2 * Hh + j_e]);
    float h_cur = __ldg(&gc[j_e]);

    // my 3 burst objects (object index == hs word-pair index)
    int o0 = tid, o1 = tid + 128, o2 = tid + 256;

    BAR128();

    int s = 0;                    // global serial step counter (== tag)

    for (int b = 0; b < BSs; b++) {
        // ---- gate on this sample's xg being fully produced by the GEMM role ----
        if (tid == 0) {
            while ((int)ldu32cg(&g_ready[b]) < 72) { }
        }
        BAR128();

        int Lb = sL[b];
        const float* xgb = g_xg + (size_t)b * Tt * G3;
        for (int t = 0; t < Lb; t++) {
            // prefetch this step's xg for my element (overlaps the wait)
            float xr = 0.f, xz = 0.f, xn = 0.f;
            if (lane < 2) {
                const float* x = xgb + (size_t)t * G3 + j_e;
                xr = __ldg(x);
                xz = __ldg(x + Hh);
                xn = __ldg(x + 2 * Hh);
            }

            // ---- 1. counter hint: thread0 polls one word chip-wide ----
            if (tid == 0) {
                unsigned tgt = (unsigned)NCTA * (unsigned)(s + 1);
                while ((int)(ldu32cg(&g_ctr) - tgt) < 0) { }
            }
            BAR128();   // B1: h_s (almost certainly) published

            // ---- 2. burst tagged read; reissue only stale objects ----
            float* hsp = hs[s & 1];
            const ull* hb = g_hb[s & 1];
            ull thi = ((ull)(unsigned int)s) << 32;
            ull a0, a1, b0, b1, c0, c1;
            ldcg2(hb + OSTR * o0, a0, a1);
            ldcg2(hb + OSTR * o1, b0, b1);
            ldcg2(hb + OSTR * o2, c0, c1);
            bool d0 = false, d1 = false, d2 = false;
            for (;;) {
                if (!d0) {
                    if ((((a0 ^ thi) | (a1 ^ thi)) >> 32) == 0) {
                        hsp[2 * o0]     = __uint_as_float((unsigned int)a0);
                        hsp[2 * o0 + 1] = __uint_as_float((unsigned int)a1);
                        d0 = true;
                    } else ldcg2(hb + OSTR * o0, a0, a1);
                }
                if (!d1) {
                    if ((((b0 ^ thi) | (b1 ^ thi)) >> 32) == 0) {
                        hsp[2 * o1]     = __uint_as_float((unsigned int)b0);
                        hsp[2 * o1 + 1] = __uint_as_float((unsigned int)b1);
                        d1 = true;
                    } else ldcg2(hb + OSTR * o1, b0, b1);
                }
                if (!d2) {
                    if ((((c0 ^ thi) | (c1 ^ thi)) >> 32) == 0) {
                        hsp[2 * o2]     = __uint_as_float((unsigned int)c0);
                        hsp[2 * o2 + 1] = __uint_as_float((unsigned int)c1);
                        d2 = true;
                    } else ldcg2(hb + OSTR * o2, c0, c1);
                }
                if (d0 && d1 && d2) break;
            }
            BAR128();   // B2: hs[s&1] fully staged

            // ---- 3. dot-partials for my parity element (72 f32x2 FMAs) ----
            ull acc0 = 0ull, acc1 = 0ull, acc2 = 0ull;
            const ull* hp = (const ull*)hsp;
#pragma unroll
            for (int k = 0; k < 24; k++) {
                ull hv = hp[m + 16 * k];
                fma2(acc0, w[0][k], hv);
                fma2(acc2, w[2][k], hv);
                fma2(acc1, w[1][k], hv);
            }
            float l0, h0, l1, h1, l2, h2;
            unpack2(acc0, l0, h0);
            unpack2(acc2, l2, h2);
            unpack2(acc1, l1, h1);
            float x0 = l0 + h0;   // r partial
            float x2 = l2 + h2;   // n partial
            float x1 = l1 + h1;   // z partial
#pragma unroll
            for (int o = 16; o >= 2; o >>= 1) {
                x0 += __shfl_xor_sync(0xFFFFFFFFu, x0, o);
                x2 += __shfl_xor_sync(0xFFFFFFFFu, x2, o);
                x1 += __shfl_xor_sync(0xFFFFFFFFu, x1, o);
            }
            // lanes of parity e hold element j_e's full sums

            // ---- 4. gates (lanes 0/1 meaningful) ----
            float r  = sigf(xr + x0 + bh0);
            float nn = tanh_fast(xn + r * (x2 + bh2));
            float z  = sigf(xz + x1 + bh1);
            float hn = fmaf(z, h_cur - nn, nn);   // (1-z)*n + z*h
            h_cur = hn;

            // ---- 5. publish 16B tagged v2 per warp; ONE red per CTA (thread0) ----
            float hn1 = __shfl_sync(0xFFFFFFFFu, hn, 1);
            if (lane == 0) {
                ull thi1 = ((ull)(unsigned int)(s + 1)) << 32;
                ull pv0 = thi1 | (ull)__float_as_uint(hn);
                ull pv1 = thi1 | (ull)__float_as_uint(hn1);
                stcg2(&g_hb[(s + 1) & 1][OSTR * myobj], pv0, pv1);
                if (tid == 0) redadd(&g_ctr);   // hint only; tags carry correctness
            }
            s++;
        }
        if (lane < 2) out[b * Hh + j_e] = h_cur;   // per-sample final hidden state
    }
    if (lane < 2 && out_size >= BSs * Hh + Hh)
        out[BSs * Hh + j_e] = h_cur;               // detached final context hF
}

// ---------------- launch ----------------
extern "C" void kernel_launch(void* const* d_in, const int* in_sizes, int n_in,
                              void* d_out, int out_size) {
    const float* emb  = (const float*)d_in[0];
    const int*   mask = (const int*)d_in[1];   // int64 in source -> int32 under JAX default
    const float* gc   = (const float*)d_in[2];
    const float* Wih  = (const float*)d_in[3];
    const float* Whh  = (const float*)d_in[4];
    const float* bih  = (const float*)d_in[5];
    const float* bhh  = (const float*)d_in[6];
    float* out = (float*)d_out;

    k_prep<<<BSs + 1, 256>>>(mask, gc);
    k_main<<<NCTA + GCTA, 256>>>(emb, gc, Wih, bih, Whh, bhh, out, out_size);
}